// round 12
// baseline (speedup 1.0000x reference)
#include <cuda_runtime.h>
#include <math.h>
#include <stdint.h>

#define SEQ 512
#define BSZ 128
#define EMBD 128
#define HID 128
#define HG  512     // 4*H
#define TAGS 7
#define BOS 4
#define EOS 5

// ---------------- scratch (static device arrays; no allocation) ----------------
__device__ float g_xw[2][SEQ][BSZ][HG];    // input projections (both dirs)
__device__ float g_hs[2][SEQ][BSZ][HID];   // hidden states fwd/bwd
__device__ float g_fts[SEQ][BSZ][8];       // tag logits (padded to 8)

// fast sigmoid/tanh on the MUFU path (rel err ~1e-7, budget is 1e-3)
__device__ __forceinline__ float fsig(float x) {
    return __fdividef(1.0f, 1.0f + __expf(-x));
}
__device__ __forceinline__ float ftanh(float x) {
    // 1 - 2/(e^{2x}+1): exact at both saturations, no inf/inf
    return 1.0f - __fdividef(2.0f, __expf(2.0f * x) + 1.0f);
}

// ================= K1: embedding gather + input projection GEMM (R2-proven) =================
__global__ __launch_bounds__(256) void k_inproj(
    const int* __restrict__ sen, const float* __restrict__ emb,
    const float* __restrict__ Wf, const float* __restrict__ bf,
    const float* __restrict__ Wb, const float* __restrict__ bb)
{
    __shared__ float As[32][64];   // k-major A tile
    __shared__ float Bs[32][64];   // k-major B tile
    __shared__ int   tok[64];

    const int tid = threadIdx.x;
    const int row0 = blockIdx.x * 64;
    const int col0 = blockIdx.y * 64;           // global col in [0,1024)
    const int dir  = col0 >> 9;
    const int g0   = col0 & 511;
    const float* __restrict__ W    = dir ? Wb : Wf;
    const float* __restrict__ bias = dir ? bb : bf;

    if (tid < 64) tok[tid] = sen[row0 + tid];
    __syncthreads();

    float acc[4][4];
#pragma unroll
    for (int i = 0; i < 4; i++)
#pragma unroll
        for (int j = 0; j < 4; j++) acc[i][j] = 0.0f;

    const int ty = tid >> 4, tx = tid & 15;
    const int lr = tid >> 2;              // 0..63
    const int kp = (tid & 3) * 8;         // 0,8,16,24

    for (int kc = 0; kc < 128; kc += 32) {
        {
            const float* src = emb + (long)tok[lr] * EMBD + kc + kp;
            float4 v0 = *(const float4*)(src);
            float4 v1 = *(const float4*)(src + 4);
            As[kp + 0][lr] = v0.x; As[kp + 1][lr] = v0.y;
            As[kp + 2][lr] = v0.z; As[kp + 3][lr] = v0.w;
            As[kp + 4][lr] = v1.x; As[kp + 5][lr] = v1.y;
            As[kp + 6][lr] = v1.z; As[kp + 7][lr] = v1.w;
        }
        {
            const float* src = W + (long)(g0 + lr) * EMBD + kc + kp;
            float4 v0 = *(const float4*)(src);
            float4 v1 = *(const float4*)(src + 4);
            Bs[kp + 0][lr] = v0.x; Bs[kp + 1][lr] = v0.y;
            Bs[kp + 2][lr] = v0.z; Bs[kp + 3][lr] = v0.w;
            Bs[kp + 4][lr] = v1.x; Bs[kp + 5][lr] = v1.y;
            Bs[kp + 6][lr] = v1.z; Bs[kp + 7][lr] = v1.w;
        }
        __syncthreads();
#pragma unroll
        for (int k = 0; k < 32; k++) {
            float4 a = *(const float4*)&As[k][ty * 4];
            float4 b = *(const float4*)&Bs[k][tx * 4];
            float av[4] = {a.x, a.y, a.z, a.w};
            float bv[4] = {b.x, b.y, b.z, b.w};
#pragma unroll
            for (int i = 0; i < 4; i++)
#pragma unroll
                for (int j = 0; j < 4; j++) acc[i][j] += av[i] * bv[j];
        }
        __syncthreads();
    }

    float4 bi = *(const float4*)&bias[g0 + tx * 4];
#pragma unroll
    for (int i = 0; i < 4; i++) {
        int R = row0 + ty * 4 + i;
        int s = R >> 7, b = R & 127;
        float4 o;
        o.x = acc[i][0] + bi.x;
        o.y = acc[i][1] + bi.y;
        o.z = acc[i][2] + bi.z;
        o.w = acc[i][3] + bi.w;
        *(float4*)&g_xw[dir][s][b][g0 + tx * 4] = o;
    }
}

// ================= K2: fused-gate LSTM recurrence =================
// 128 blocks: dir = bid>>6, batch pair = (bid&63)*2. 128 threads: thread t = hid unit t.
// Thread computes gates i,f,g,o for its unit (rows t,128+t,256+t,384+t) for BOTH batch
// elems, then its own pointwise + h write. One barrier per step, h double-buffered.
__global__ __launch_bounds__(128) void k_lstm(
    const float* __restrict__ Whh_f, const float* __restrict__ Whh_b)
{
    const int bid = blockIdx.x;
    const int dir = bid >> 6;
    const int b0  = (bid & 63) * 2;
    const float* __restrict__ Whh = dir ? Whh_b : Whh_f;

    const int t = threadIdx.x;             // hid unit
    __shared__ __align__(16) float hbuf[2][2][HID];   // [pingpong][batch][hid]

    hbuf[0][0][t] = 0.0f;
    hbuf[0][1][t] = 0.0f;
    float c0 = 0.0f, c1 = 0.0f;
    __syncthreads();

    const float4* __restrict__ Wi = (const float4*)(Whh + (long)(t)       * HID);
    const float4* __restrict__ Wf = (const float4*)(Whh + (long)(128 + t) * HID);
    const float4* __restrict__ Wg = (const float4*)(Whh + (long)(256 + t) * HID);
    const float4* __restrict__ Wo = (const float4*)(Whh + (long)(384 + t) * HID);

    int buf = 0;
    for (int step = 0; step < SEQ; ++step) {
        const int s = dir ? (SEQ - 1 - step) : step;
        const float* __restrict__ xwp = &g_xw[dir][s][b0][0];

        // xw loads issued up front; consumed only after the dot loop (latency hidden)
        float xi0 = xwp[t],       xf0 = xwp[128 + t], xg0 = xwp[256 + t], xo0 = xwp[384 + t];
        float xi1 = xwp[512 + t], xf1 = xwp[640 + t], xg1 = xwp[768 + t], xo1 = xwp[896 + t];

        const float4* h0 = (const float4*)hbuf[buf][0];
        const float4* h1 = (const float4*)hbuf[buf][1];

        float ai0 = 0.f, af0 = 0.f, ag0 = 0.f, ao0 = 0.f;
        float ai1 = 0.f, af1 = 0.f, ag1 = 0.f, ao1 = 0.f;
#pragma unroll
        for (int k = 0; k < 32; k++) {
            float4 wi = Wi[k], wf = Wf[k], wg = Wg[k], wo = Wo[k];
            float4 p = h0[k], q = h1[k];
            ai0 += wi.x * p.x + wi.y * p.y + wi.z * p.z + wi.w * p.w;
            ai1 += wi.x * q.x + wi.y * q.y + wi.z * q.z + wi.w * q.w;
            af0 += wf.x * p.x + wf.y * p.y + wf.z * p.z + wf.w * p.w;
            af1 += wf.x * q.x + wf.y * q.y + wf.z * q.z + wf.w * q.w;
            ag0 += wg.x * p.x + wg.y * p.y + wg.z * p.z + wg.w * p.w;
            ag1 += wg.x * q.x + wg.y * q.y + wg.z * q.z + wg.w * q.w;
            ao0 += wo.x * p.x + wo.y * p.y + wo.z * p.z + wo.w * p.w;
            ao1 += wo.x * q.x + wo.y * q.y + wo.z * q.z + wo.w * q.w;
        }

        // pointwise, fully in registers
        c0 = fsig(af0 + xf0) * c0 + fsig(ai0 + xi0) * ftanh(ag0 + xg0);
        c1 = fsig(af1 + xf1) * c1 + fsig(ai1 + xi1) * ftanh(ag1 + xg1);
        float nh0 = fsig(ao0 + xo0) * ftanh(c0);
        float nh1 = fsig(ao1 + xo1) * ftanh(c1);

        buf ^= 1;
        hbuf[buf][0][t] = nh0;
        hbuf[buf][1][t] = nh1;
        g_hs[dir][s][b0][t]       = nh0;
        g_hs[dir][s][b0][HID + t] = nh1;
        __syncthreads();
    }
}

// ================= K3: hid2tag logits =================
__global__ __launch_bounds__(256) void k_fts(
    const float* __restrict__ W_out, const float* __restrict__ b_out)
{
    __shared__ float Ws[TAGS * 256];
    __shared__ float bs[TAGS];
    const int tid = threadIdx.x;
    for (int i = tid; i < TAGS * 256; i += 256) Ws[i] = W_out[i];
    if (tid < TAGS) bs[tid] = b_out[tid];
    __syncthreads();

    const int warp = tid >> 5, lane = tid & 31;
    const int rb = blockIdx.x * 8 + warp;
    const int s = rb >> 7, b = rb & 127;

    float4 hf = ((const float4*)&g_hs[0][s][b][0])[lane];
    float4 hb = ((const float4*)&g_hs[1][s][b][0])[lane];

    float mine = 0.0f;
#pragma unroll
    for (int T = 0; T < TAGS; T++) {
        const float* w = &Ws[T * 256];
        float4 wa = *(const float4*)&w[lane * 4];
        float4 wb = *(const float4*)&w[128 + lane * 4];
        float p = hf.x * wa.x + hf.y * wa.y + hf.z * wa.z + hf.w * wa.w
                + hb.x * wb.x + hb.y * wb.y + hb.z * wb.z + hb.w * wb.w;
#pragma unroll
        for (int o = 16; o > 0; o >>= 1) p += __shfl_xor_sync(0xffffffffu, p, o);
        if (lane == T) mine = p;
    }
    if (lane < TAGS) g_fts[s][b][lane] = mine + bs[lane];
}

// ================= K4: Viterbi forward + backtrace =================
__global__ __launch_bounds__(64) void k_viterbi(
    const float* __restrict__ trans, float* __restrict__ out, int out_size)
{
    const int b = blockIdx.x;
    __shared__ float sft[SEQ][TAGS];
    __shared__ unsigned char bp[SEQ][8];
    const int tid = threadIdx.x;

    for (int i = tid; i < SEQ * TAGS; i += 64) {
        int s = i / TAGS, T = i % TAGS;
        sft[s][T] = g_fts[s][b][T];
    }
    __syncthreads();
    if (tid >= 32) return;

    const int lane = tid;
    const int j = (lane < TAGS) ? lane : (TAGS - 1);
    float tr[TAGS];
#pragma unroll
    for (int p = 0; p < TAGS; p++) tr[p] = trans[j * TAGS + p];

    float fv = (lane == BOS) ? 0.0f : -10000.0f;

    for (int s = 0; s < SEQ; s++) {
        float best = -3.4e38f;
        int bi = 0;
#pragma unroll
        for (int p = 0; p < TAGS; p++) {
            float fvp = __shfl_sync(0xffffffffu, fv, p);
            float sc = fvp + tr[p];
            if (sc > best) { best = sc; bi = p; }   // strict > : first-max argmax
        }
        if (lane < TAGS) {
            bp[s][lane] = (unsigned char)bi;
            fv = best + sft[s][lane];
        }
    }

    float term = fv + trans[EOS * TAGS + j];
    float bestv = -3.4e38f;
    int bidx = 0;
#pragma unroll
    for (int p = 0; p < TAGS; p++) {
        float tv = __shfl_sync(0xffffffffu, term, p);
        if (tv > bestv) { bestv = tv; bidx = p; }
    }

    if (lane == 0) {
        int tagbase = -1;
        bool write_score = false;
        if (out_size >= 128 + SEQ * BSZ) { write_score = true; tagbase = 128; }
        else if (out_size >= SEQ * BSZ)  { tagbase = 0; }
        else                             { write_score = true; }

        if (write_score) out[b] = bestv;
        if (tagbase >= 0) {
            int cur = bidx;
            for (int s = SEQ - 1; s >= 0; s--) {
                out[tagbase + s * BSZ + b] = (float)cur;
                cur = bp[s][cur];
            }
        }
    }
}

// ================= launcher =================
extern "C" void kernel_launch(void* const* d_in, const int* in_sizes, int n_in,
                              void* d_out, int out_size)
{
    const int*   sen   = (const int*)  d_in[0];
    const float* emb   = (const float*)d_in[1];
    const float* Wih_f = (const float*)d_in[2];
    const float* Whh_f = (const float*)d_in[3];
    const float* b_f   = (const float*)d_in[4];
    const float* Wih_b = (const float*)d_in[5];
    const float* Whh_b = (const float*)d_in[6];
    const float* b_b   = (const float*)d_in[7];
    const float* W_out = (const float*)d_in[8];
    const float* b_out = (const float*)d_in[9];
    const float* trans = (const float*)d_in[10];
    float* out = (float*)d_out;

    dim3 g1(1024, 16);
    k_inproj<<<g1, 256>>>(sen, emb, Wih_f, b_f, Wih_b, b_b);
    k_lstm<<<128, 128>>>(Whh_f, Whh_b);
    k_fts<<<8192, 256>>>(W_out, b_out);
    k_viterbi<<<128, 64>>>(trans, out, out_size);
}

// round 13
// speedup vs baseline: 1.0011x; 1.0011x over previous
#include <cuda_runtime.h>
#include <math.h>
#include <stdint.h>

#define SEQ 512
#define BSZ 128
#define EMBD 128
#define HID 128
#define HG  512     // 4*H
#define TAGS 7
#define BOS 4
#define EOS 5

// ---------------- scratch (static device arrays; no allocation) ----------------
__device__ float g_xw[2][SEQ][BSZ][HG];    // input projections (both dirs)
__device__ float g_hs[2][SEQ][BSZ][HID];   // hidden states fwd/bwd
__device__ float g_fts[SEQ][BSZ][8];       // tag logits (padded to 8)

// fast sigmoid/tanh on the MUFU path (rel err ~1e-7, budget is 1e-3)
__device__ __forceinline__ float fsig(float x) {
    return __fdividef(1.0f, 1.0f + __expf(-x));
}
__device__ __forceinline__ float ftanh(float x) {
    // 1 - 2/(e^{2x}+1): exact at both saturations, no inf/inf
    return 1.0f - __fdividef(2.0f, __expf(2.0f * x) + 1.0f);
}

// ================= K1: embedding gather + input projection GEMM (R2-proven) =================
__global__ __launch_bounds__(256) void k_inproj(
    const int* __restrict__ sen, const float* __restrict__ emb,
    const float* __restrict__ Wf, const float* __restrict__ bf,
    const float* __restrict__ Wb, const float* __restrict__ bb)
{
    __shared__ float As[32][64];   // k-major A tile
    __shared__ float Bs[32][64];   // k-major B tile
    __shared__ int   tok[64];

    const int tid = threadIdx.x;
    const int row0 = blockIdx.x * 64;
    const int col0 = blockIdx.y * 64;           // global col in [0,1024)
    const int dir  = col0 >> 9;
    const int g0   = col0 & 511;
    const float* __restrict__ W    = dir ? Wb : Wf;
    const float* __restrict__ bias = dir ? bb : bf;

    if (tid < 64) tok[tid] = sen[row0 + tid];
    __syncthreads();

    float acc[4][4];
#pragma unroll
    for (int i = 0; i < 4; i++)
#pragma unroll
        for (int j = 0; j < 4; j++) acc[i][j] = 0.0f;

    const int ty = tid >> 4, tx = tid & 15;
    const int lr = tid >> 2;              // 0..63
    const int kp = (tid & 3) * 8;         // 0,8,16,24

    for (int kc = 0; kc < 128; kc += 32) {
        {
            const float* src = emb + (long)tok[lr] * EMBD + kc + kp;
            float4 v0 = *(const float4*)(src);
            float4 v1 = *(const float4*)(src + 4);
            As[kp + 0][lr] = v0.x; As[kp + 1][lr] = v0.y;
            As[kp + 2][lr] = v0.z; As[kp + 3][lr] = v0.w;
            As[kp + 4][lr] = v1.x; As[kp + 5][lr] = v1.y;
            As[kp + 6][lr] = v1.z; As[kp + 7][lr] = v1.w;
        }
        {
            const float* src = W + (long)(g0 + lr) * EMBD + kc + kp;
            float4 v0 = *(const float4*)(src);
            float4 v1 = *(const float4*)(src + 4);
            Bs[kp + 0][lr] = v0.x; Bs[kp + 1][lr] = v0.y;
            Bs[kp + 2][lr] = v0.z; Bs[kp + 3][lr] = v0.w;
            Bs[kp + 4][lr] = v1.x; Bs[kp + 5][lr] = v1.y;
            Bs[kp + 6][lr] = v1.z; Bs[kp + 7][lr] = v1.w;
        }
        __syncthreads();
#pragma unroll
        for (int k = 0; k < 32; k++) {
            float4 a = *(const float4*)&As[k][ty * 4];
            float4 b = *(const float4*)&Bs[k][tx * 4];
            float av[4] = {a.x, a.y, a.z, a.w};
            float bv[4] = {b.x, b.y, b.z, b.w};
#pragma unroll
            for (int i = 0; i < 4; i++)
#pragma unroll
                for (int j = 0; j < 4; j++) acc[i][j] += av[i] * bv[j];
        }
        __syncthreads();
    }

    float4 bi = *(const float4*)&bias[g0 + tx * 4];
#pragma unroll
    for (int i = 0; i < 4; i++) {
        int R = row0 + ty * 4 + i;
        int s = R >> 7, b = R & 127;
        float4 o;
        o.x = acc[i][0] + bi.x;
        o.y = acc[i][1] + bi.y;
        o.z = acc[i][2] + bi.z;
        o.w = acc[i][3] + bi.w;
        *(float4*)&g_xw[dir][s][b][g0 + tx * 4] = o;
    }
}

// ================= K2: fused-gate LSTM recurrence =================
// 128 blocks: dir = bid>>6, batch pair = (bid&63)*2. 128 threads: thread t = hid unit t.
// Thread computes gates i,f,g,o for its unit (rows t,128+t,256+t,384+t) for BOTH batch
// elems, then its own pointwise + h write. One barrier per step, h double-buffered.
__global__ __launch_bounds__(128) void k_lstm(
    const float* __restrict__ Whh_f, const float* __restrict__ Whh_b)
{
    const int bid = blockIdx.x;
    const int dir = bid >> 6;
    const int b0  = (bid & 63) * 2;
    const float* __restrict__ Whh = dir ? Whh_b : Whh_f;

    const int t = threadIdx.x;             // hid unit
    __shared__ __align__(16) float hbuf[2][2][HID];   // [pingpong][batch][hid]

    hbuf[0][0][t] = 0.0f;
    hbuf[0][1][t] = 0.0f;
    float c0 = 0.0f, c1 = 0.0f;
    __syncthreads();

    const float4* __restrict__ Wi = (const float4*)(Whh + (long)(t)       * HID);
    const float4* __restrict__ Wf = (const float4*)(Whh + (long)(128 + t) * HID);
    const float4* __restrict__ Wg = (const float4*)(Whh + (long)(256 + t) * HID);
    const float4* __restrict__ Wo = (const float4*)(Whh + (long)(384 + t) * HID);

    int buf = 0;
    for (int step = 0; step < SEQ; ++step) {
        const int s = dir ? (SEQ - 1 - step) : step;
        const float* __restrict__ xwp = &g_xw[dir][s][b0][0];

        // xw loads issued up front; consumed only after the dot loop (latency hidden)
        float xi0 = xwp[t],       xf0 = xwp[128 + t], xg0 = xwp[256 + t], xo0 = xwp[384 + t];
        float xi1 = xwp[512 + t], xf1 = xwp[640 + t], xg1 = xwp[768 + t], xo1 = xwp[896 + t];

        const float4* h0 = (const float4*)hbuf[buf][0];
        const float4* h1 = (const float4*)hbuf[buf][1];

        float ai0 = 0.f, af0 = 0.f, ag0 = 0.f, ao0 = 0.f;
        float ai1 = 0.f, af1 = 0.f, ag1 = 0.f, ao1 = 0.f;
#pragma unroll
        for (int k = 0; k < 32; k++) {
            float4 wi = Wi[k], wf = Wf[k], wg = Wg[k], wo = Wo[k];
            float4 p = h0[k], q = h1[k];
            ai0 += wi.x * p.x + wi.y * p.y + wi.z * p.z + wi.w * p.w;
            ai1 += wi.x * q.x + wi.y * q.y + wi.z * q.z + wi.w * q.w;
            af0 += wf.x * p.x + wf.y * p.y + wf.z * p.z + wf.w * p.w;
            af1 += wf.x * q.x + wf.y * q.y + wf.z * q.z + wf.w * q.w;
            ag0 += wg.x * p.x + wg.y * p.y + wg.z * p.z + wg.w * p.w;
            ag1 += wg.x * q.x + wg.y * q.y + wg.z * q.z + wg.w * q.w;
            ao0 += wo.x * p.x + wo.y * p.y + wo.z * p.z + wo.w * p.w;
            ao1 += wo.x * q.x + wo.y * q.y + wo.z * q.z + wo.w * q.w;
        }

        // pointwise, fully in registers
        c0 = fsig(af0 + xf0) * c0 + fsig(ai0 + xi0) * ftanh(ag0 + xg0);
        c1 = fsig(af1 + xf1) * c1 + fsig(ai1 + xi1) * ftanh(ag1 + xg1);
        float nh0 = fsig(ao0 + xo0) * ftanh(c0);
        float nh1 = fsig(ao1 + xo1) * ftanh(c1);

        buf ^= 1;
        hbuf[buf][0][t] = nh0;
        hbuf[buf][1][t] = nh1;
        g_hs[dir][s][b0][t]       = nh0;
        g_hs[dir][s][b0][HID + t] = nh1;
        __syncthreads();
    }
}

// ================= K3: hid2tag logits =================
__global__ __launch_bounds__(256) void k_fts(
    const float* __restrict__ W_out, const float* __restrict__ b_out)
{
    __shared__ float Ws[TAGS * 256];
    __shared__ float bs[TAGS];
    const int tid = threadIdx.x;
    for (int i = tid; i < TAGS * 256; i += 256) Ws[i] = W_out[i];
    if (tid < TAGS) bs[tid] = b_out[tid];
    __syncthreads();

    const int warp = tid >> 5, lane = tid & 31;
    const int rb = blockIdx.x * 8 + warp;
    const int s = rb >> 7, b = rb & 127;

    float4 hf = ((const float4*)&g_hs[0][s][b][0])[lane];
    float4 hb = ((const float4*)&g_hs[1][s][b][0])[lane];

    float mine = 0.0f;
#pragma unroll
    for (int T = 0; T < TAGS; T++) {
        const float* w = &Ws[T * 256];
        float4 wa = *(const float4*)&w[lane * 4];
        float4 wb = *(const float4*)&w[128 + lane * 4];
        float p = hf.x * wa.x + hf.y * wa.y + hf.z * wa.z + hf.w * wa.w
                + hb.x * wb.x + hb.y * wb.y + hb.z * wb.z + hb.w * wb.w;
#pragma unroll
        for (int o = 16; o > 0; o >>= 1) p += __shfl_xor_sync(0xffffffffu, p, o);
        if (lane == T) mine = p;
    }
    if (lane < TAGS) g_fts[s][b][lane] = mine + bs[lane];
}

// ================= K4: Viterbi forward + backtrace =================
__global__ __launch_bounds__(64) void k_viterbi(
    const float* __restrict__ trans, float* __restrict__ out, int out_size)
{
    const int b = blockIdx.x;
    __shared__ float sft[SEQ][TAGS];
    __shared__ unsigned char bp[SEQ][8];
    const int tid = threadIdx.x;

    for (int i = tid; i < SEQ * TAGS; i += 64) {
        int s = i / TAGS, T = i % TAGS;
        sft[s][T] = g_fts[s][b][T];
    }
    __syncthreads();
    if (tid >= 32) return;

    const int lane = tid;
    const int j = (lane < TAGS) ? lane : (TAGS - 1);
    float tr[TAGS];
#pragma unroll
    for (int p = 0; p < TAGS; p++) tr[p] = trans[j * TAGS + p];

    float fv = (lane == BOS) ? 0.0f : -10000.0f;

    for (int s = 0; s < SEQ; s++) {
        float best = -3.4e38f;
        int bi = 0;
#pragma unroll
        for (int p = 0; p < TAGS; p++) {
            float fvp = __shfl_sync(0xffffffffu, fv, p);
            float sc = fvp + tr[p];
            if (sc > best) { best = sc; bi = p; }   // strict > : first-max argmax
        }
        if (lane < TAGS) {
            bp[s][lane] = (unsigned char)bi;
            fv = best + sft[s][lane];
        }
    }

    float term = fv + trans[EOS * TAGS + j];
    float bestv = -3.4e38f;
    int bidx = 0;
#pragma unroll
    for (int p = 0; p < TAGS; p++) {
        float tv = __shfl_sync(0xffffffffu, term, p);
        if (tv > bestv) { bestv = tv; bidx = p; }
    }

    if (lane == 0) {
        int tagbase = -1;
        bool write_score = false;
        if (out_size >= 128 + SEQ * BSZ) { write_score = true; tagbase = 128; }
        else if (out_size >= SEQ * BSZ)  { tagbase = 0; }
        else                             { write_score = true; }

        if (write_score) out[b] = bestv;
        if (tagbase >= 0) {
            int cur = bidx;
            for (int s = SEQ - 1; s >= 0; s--) {
                out[tagbase + s * BSZ + b] = (float)cur;
                cur = bp[s][cur];
            }
        }
    }
}

// ================= launcher =================
extern "C" void kernel_launch(void* const* d_in, const int* in_sizes, int n_in,
                              void* d_out, int out_size)
{
    const int*   sen   = (const int*)  d_in[0];
    const float* emb   = (const float*)d_in[1];
    const float* Wih_f = (const float*)d_in[2];
    const float* Whh_f = (const float*)d_in[3];
    const float* b_f   = (const float*)d_in[4];
    const float* Wih_b = (const float*)d_in[5];
    const float* Whh_b = (const float*)d_in[6];
    const float* b_b   = (const float*)d_in[7];
    const float* W_out = (const float*)d_in[8];
    const float* b_out = (const float*)d_in[9];
    const float* trans = (const float*)d_in[10];
    float* out = (float*)d_out;

    dim3 g1(1024, 16);
    k_inproj<<<g1, 256>>>(sen, emb, Wih_f, b_f, Wih_b, b_b);
    k_lstm<<<128, 128>>>(Whh_f, Whh_b);
    k_fts<<<8192, 256>>>(W_out, b_out);
    k_viterbi<<<128, 64>>>(trans, out, out_size);
}

// round 14
// speedup vs baseline: 1.0088x; 1.0077x over previous
#include <cuda_runtime.h>
#include <math.h>
#include <stdint.h>

#define SEQ 512
#define BSZ 128
#define EMBD 128
#define HID 128
#define HG  512     // 4*H
#define TAGS 7
#define BOS 4
#define EOS 5

// ---------------- scratch (static device arrays; no allocation) ----------------
__device__ float g_xw[2][SEQ][BSZ][HG];    // input projections (both dirs)
__device__ float g_hs[2][SEQ][BSZ][HID];   // hidden states fwd/bwd
__device__ float g_fts[SEQ][BSZ][8];       // tag logits (padded to 8)

// fast sigmoid/tanh on the MUFU path (rel err ~1e-7, budget is 1e-3)
__device__ __forceinline__ float fsig(float x) {
    return __fdividef(1.0f, 1.0f + __expf(-x));
}
__device__ __forceinline__ float ftanh(float x) {
    // 1 - 2/(e^{2x}+1): exact at both saturations, no inf/inf
    return 1.0f - __fdividef(2.0f, __expf(2.0f * x) + 1.0f);
}

// ================= K1: embedding gather + input projection GEMM (R2-proven) =================
__global__ __launch_bounds__(256) void k_inproj(
    const int* __restrict__ sen, const float* __restrict__ emb,
    const float* __restrict__ Wf, const float* __restrict__ bf,
    const float* __restrict__ Wb, const float* __restrict__ bb)
{
    __shared__ float As[32][64];   // k-major A tile
    __shared__ float Bs[32][64];   // k-major B tile
    __shared__ int   tok[64];

    const int tid = threadIdx.x;
    const int row0 = blockIdx.x * 64;
    const int col0 = blockIdx.y * 64;           // global col in [0,1024)
    const int dir  = col0 >> 9;
    const int g0   = col0 & 511;
    const float* __restrict__ W    = dir ? Wb : Wf;
    const float* __restrict__ bias = dir ? bb : bf;

    if (tid < 64) tok[tid] = sen[row0 + tid];
    __syncthreads();

    float acc[4][4];
#pragma unroll
    for (int i = 0; i < 4; i++)
#pragma unroll
        for (int j = 0; j < 4; j++) acc[i][j] = 0.0f;

    const int ty = tid >> 4, tx = tid & 15;
    const int lr = tid >> 2;              // 0..63
    const int kp = (tid & 3) * 8;         // 0,8,16,24

    for (int kc = 0; kc < 128; kc += 32) {
        {
            const float* src = emb + (long)tok[lr] * EMBD + kc + kp;
            float4 v0 = *(const float4*)(src);
            float4 v1 = *(const float4*)(src + 4);
            As[kp + 0][lr] = v0.x; As[kp + 1][lr] = v0.y;
            As[kp + 2][lr] = v0.z; As[kp + 3][lr] = v0.w;
            As[kp + 4][lr] = v1.x; As[kp + 5][lr] = v1.y;
            As[kp + 6][lr] = v1.z; As[kp + 7][lr] = v1.w;
        }
        {
            const float* src = W + (long)(g0 + lr) * EMBD + kc + kp;
            float4 v0 = *(const float4*)(src);
            float4 v1 = *(const float4*)(src + 4);
            Bs[kp + 0][lr] = v0.x; Bs[kp + 1][lr] = v0.y;
            Bs[kp + 2][lr] = v0.z; Bs[kp + 3][lr] = v0.w;
            Bs[kp + 4][lr] = v1.x; Bs[kp + 5][lr] = v1.y;
            Bs[kp + 6][lr] = v1.z; Bs[kp + 7][lr] = v1.w;
        }
        __syncthreads();
#pragma unroll
        for (int k = 0; k < 32; k++) {
            float4 a = *(const float4*)&As[k][ty * 4];
            float4 b = *(const float4*)&Bs[k][tx * 4];
            float av[4] = {a.x, a.y, a.z, a.w};
            float bv[4] = {b.x, b.y, b.z, b.w};
#pragma unroll
            for (int i = 0; i < 4; i++)
#pragma unroll
                for (int j = 0; j < 4; j++) acc[i][j] += av[i] * bv[j];
        }
        __syncthreads();
    }

    float4 bi = *(const float4*)&bias[g0 + tx * 4];
#pragma unroll
    for (int i = 0; i < 4; i++) {
        int R = row0 + ty * 4 + i;
        int s = R >> 7, b = R & 127;
        float4 o;
        o.x = acc[i][0] + bi.x;
        o.y = acc[i][1] + bi.y;
        o.z = acc[i][2] + bi.z;
        o.w = acc[i][3] + bi.w;
        *(float4*)&g_xw[dir][s][b][g0 + tx * 4] = o;
    }
}

// ================= K2: fused-gate LSTM recurrence =================
// 128 blocks: dir = bid>>6, batch pair = (bid&63)*2. 128 threads: thread t = hid unit t.
// Thread computes gates i,f,g,o for its unit (rows t,128+t,256+t,384+t) for BOTH batch
// elems, then its own pointwise + h write. One barrier per step, h double-buffered.
__global__ __launch_bounds__(128) void k_lstm(
    const float* __restrict__ Whh_f, const float* __restrict__ Whh_b)
{
    const int bid = blockIdx.x;
    const int dir = bid >> 6;
    const int b0  = (bid & 63) * 2;
    const float* __restrict__ Whh = dir ? Whh_b : Whh_f;

    const int t = threadIdx.x;             // hid unit
    __shared__ __align__(16) float hbuf[2][2][HID];   // [pingpong][batch][hid]

    hbuf[0][0][t] = 0.0f;
    hbuf[0][1][t] = 0.0f;
    float c0 = 0.0f, c1 = 0.0f;
    __syncthreads();

    const float4* __restrict__ Wi = (const float4*)(Whh + (long)(t)       * HID);
    const float4* __restrict__ Wf = (const float4*)(Whh + (long)(128 + t) * HID);
    const float4* __restrict__ Wg = (const float4*)(Whh + (long)(256 + t) * HID);
    const float4* __restrict__ Wo = (const float4*)(Whh + (long)(384 + t) * HID);

    int buf = 0;
    for (int step = 0; step < SEQ; ++step) {
        const int s = dir ? (SEQ - 1 - step) : step;
        const float* __restrict__ xwp = &g_xw[dir][s][b0][0];

        // xw loads issued up front; consumed only after the dot loop (latency hidden)
        float xi0 = xwp[t],       xf0 = xwp[128 + t], xg0 = xwp[256 + t], xo0 = xwp[384 + t];
        float xi1 = xwp[512 + t], xf1 = xwp[640 + t], xg1 = xwp[768 + t], xo1 = xwp[896 + t];

        const float4* h0 = (const float4*)hbuf[buf][0];
        const float4* h1 = (const float4*)hbuf[buf][1];

        float ai0 = 0.f, af0 = 0.f, ag0 = 0.f, ao0 = 0.f;
        float ai1 = 0.f, af1 = 0.f, ag1 = 0.f, ao1 = 0.f;
#pragma unroll
        for (int k = 0; k < 32; k++) {
            float4 wi = Wi[k], wf = Wf[k], wg = Wg[k], wo = Wo[k];
            float4 p = h0[k], q = h1[k];
            ai0 += wi.x * p.x + wi.y * p.y + wi.z * p.z + wi.w * p.w;
            ai1 += wi.x * q.x + wi.y * q.y + wi.z * q.z + wi.w * q.w;
            af0 += wf.x * p.x + wf.y * p.y + wf.z * p.z + wf.w * p.w;
            af1 += wf.x * q.x + wf.y * q.y + wf.z * q.z + wf.w * q.w;
            ag0 += wg.x * p.x + wg.y * p.y + wg.z * p.z + wg.w * p.w;
            ag1 += wg.x * q.x + wg.y * q.y + wg.z * q.z + wg.w * q.w;
            ao0 += wo.x * p.x + wo.y * p.y + wo.z * p.z + wo.w * p.w;
            ao1 += wo.x * q.x + wo.y * q.y + wo.z * q.z + wo.w * q.w;
        }

        // pointwise, fully in registers
        c0 = fsig(af0 + xf0) * c0 + fsig(ai0 + xi0) * ftanh(ag0 + xg0);
        c1 = fsig(af1 + xf1) * c1 + fsig(ai1 + xi1) * ftanh(ag1 + xg1);
        float nh0 = fsig(ao0 + xo0) * ftanh(c0);
        float nh1 = fsig(ao1 + xo1) * ftanh(c1);

        buf ^= 1;
        hbuf[buf][0][t] = nh0;
        hbuf[buf][1][t] = nh1;
        g_hs[dir][s][b0][t]       = nh0;
        g_hs[dir][s][b0][HID + t] = nh1;
        __syncthreads();
    }
}

// ================= K3: hid2tag logits =================
__global__ __launch_bounds__(256) void k_fts(
    const float* __restrict__ W_out, const float* __restrict__ b_out)
{
    __shared__ float Ws[TAGS * 256];
    __shared__ float bs[TAGS];
    const int tid = threadIdx.x;
    for (int i = tid; i < TAGS * 256; i += 256) Ws[i] = W_out[i];
    if (tid < TAGS) bs[tid] = b_out[tid];
    __syncthreads();

    const int warp = tid >> 5, lane = tid & 31;
    const int rb = blockIdx.x * 8 + warp;
    const int s = rb >> 7, b = rb & 127;

    float4 hf = ((const float4*)&g_hs[0][s][b][0])[lane];
    float4 hb = ((const float4*)&g_hs[1][s][b][0])[lane];

    float mine = 0.0f;
#pragma unroll
    for (int T = 0; T < TAGS; T++) {
        const float* w = &Ws[T * 256];
        float4 wa = *(const float4*)&w[lane * 4];
        float4 wb = *(const float4*)&w[128 + lane * 4];
        float p = hf.x * wa.x + hf.y * wa.y + hf.z * wa.z + hf.w * wa.w
                + hb.x * wb.x + hb.y * wb.y + hb.z * wb.z + hb.w * wb.w;
#pragma unroll
        for (int o = 16; o > 0; o >>= 1) p += __shfl_xor_sync(0xffffffffu, p, o);
        if (lane == T) mine = p;
    }
    if (lane < TAGS) g_fts[s][b][lane] = mine + bs[lane];
}

// ================= K4: Viterbi forward + backtrace =================
__global__ __launch_bounds__(64) void k_viterbi(
    const float* __restrict__ trans, float* __restrict__ out, int out_size)
{
    const int b = blockIdx.x;
    __shared__ float sft[SEQ][TAGS];
    __shared__ unsigned char bp[SEQ][8];
    const int tid = threadIdx.x;

    for (int i = tid; i < SEQ * TAGS; i += 64) {
        int s = i / TAGS, T = i % TAGS;
        sft[s][T] = g_fts[s][b][T];
    }
    __syncthreads();
    if (tid >= 32) return;

    const int lane = tid;
    const int j = (lane < TAGS) ? lane : (TAGS - 1);
    float tr[TAGS];
#pragma unroll
    for (int p = 0; p < TAGS; p++) tr[p] = trans[j * TAGS + p];

    float fv = (lane == BOS) ? 0.0f : -10000.0f;

    for (int s = 0; s < SEQ; s++) {
        float best = -3.4e38f;
        int bi = 0;
#pragma unroll
        for (int p = 0; p < TAGS; p++) {
            float fvp = __shfl_sync(0xffffffffu, fv, p);
            float sc = fvp + tr[p];
            if (sc > best) { best = sc; bi = p; }   // strict > : first-max argmax
        }
        if (lane < TAGS) {
            bp[s][lane] = (unsigned char)bi;
            fv = best + sft[s][lane];
        }
    }

    float term = fv + trans[EOS * TAGS + j];
    float bestv = -3.4e38f;
    int bidx = 0;
#pragma unroll
    for (int p = 0; p < TAGS; p++) {
        float tv = __shfl_sync(0xffffffffu, term, p);
        if (tv > bestv) { bestv = tv; bidx = p; }
    }

    if (lane == 0) {
        int tagbase = -1;
        bool write_score = false;
        if (out_size >= 128 + SEQ * BSZ) { write_score = true; tagbase = 128; }
        else if (out_size >= SEQ * BSZ)  { tagbase = 0; }
        else                             { write_score = true; }

        if (write_score) out[b] = bestv;
        if (tagbase >= 0) {
            int cur = bidx;
            for (int s = SEQ - 1; s >= 0; s--) {
                out[tagbase + s * BSZ + b] = (float)cur;
                cur = bp[s][cur];
            }
        }
    }
}

// ================= launcher =================
extern "C" void kernel_launch(void* const* d_in, const int* in_sizes, int n_in,
                              void* d_out, int out_size)
{
    const int*   sen   = (const int*)  d_in[0];
    const float* emb   = (const float*)d_in[1];
    const float* Wih_f = (const float*)d_in[2];
    const float* Whh_f = (const float*)d_in[3];
    const float* b_f   = (const float*)d_in[4];
    const float* Wih_b = (const float*)d_in[5];
    const float* Whh_b = (const float*)d_in[6];
    const float* b_b   = (const float*)d_in[7];
    const float* W_out = (const float*)d_in[8];
    const float* b_out = (const float*)d_in[9];
    const float* trans = (const float*)d_in[10];
    float* out = (float*)d_out;

    dim3 g1(1024, 16);
    k_inproj<<<g1, 256>>>(sen, emb, Wih_f, b_f, Wih_b, b_b);
    k_lstm<<<128, 128>>>(Whh_f, Whh_b);
    k_fts<<<8192, 256>>>(W_out, b_out);
    k_viterbi<<<128, 64>>>(trans, out, out_size);
}